// round 12
// baseline (speedup 1.0000x reference)
#include <cuda_runtime.h>
#include <cstdint>
#include <cstddef>

// Problem constants (fixed-shape problem)
#define NROW 12288
#define INF  256
#define DF   128
#define TJ   32            // j-tile width in main kernel
#define RPC  32            // rows per CTA in main kernel
#define NT   (NROW / TJ)   // 384 tiles
#define APAD 36            // padded row length for P tile in SMEM

// ---------------- device scratch (static allocation only; no cudaMalloc) ----
__device__ __align__(16) float g_Wh[(size_t)NROW * DF];   // 6.29 MB
__device__ __align__(16) float g_Wh1[NROW];
__device__ __align__(16) float g_Wh2[NROW];
__device__ __align__(16) float g_E1 [NROW];   // exp(Wh1)
__device__ __align__(16) float g_E02[NROW];   // exp(0.2*Wh1)
__device__ __align__(16) float g_F1 [NROW];   // exp(Wh2)
__device__ __align__(16) float g_F02[NROW];   // exp(0.2*Wh2)

typedef unsigned long long ull;

// ---------------- packed f32x2 helpers (Blackwell FFMA2) --------------------
__device__ __forceinline__ void fma2(ull& d, ull a, ull b) {
    asm("fma.rn.f32x2 %0, %1, %2, %0;" : "+l"(d) : "l"(a), "l"(b));
}
__device__ __forceinline__ ull pack2(float x) {
    ull r; unsigned xi = __float_as_uint(x);
    asm("mov.b64 %0, {%1, %1};" : "=l"(r) : "r"(xi));
    return r;
}
__device__ __forceinline__ float2 unpack2(ull v) {
    unsigned lo, hi;
    asm("mov.b64 {%0, %1}, %2;" : "=r"(lo), "=r"(hi) : "l"(v));
    return make_float2(__uint_as_float(lo), __uint_as_float(hi));
}

// ===========================================================================
// Kernel A: Wh = h @ W   [12288,256] @ [256,128] -> g_Wh
// Tiled SGEMM: 64 rows x 128 cols per CTA, 256 threads, thread tile 4x8.
// ===========================================================================
__global__ __launch_bounds__(256) void k_wh(const float* __restrict__ h,
                                            const float* __restrict__ W) {
    __shared__ __align__(16) float hs[64 * APAD];   // [64][36]
    __shared__ __align__(16) float Ws[32 * DF];     // [32][128]

    const int t  = threadIdx.x;
    const int tx = t & 15;        // col group: cols tx*8 .. tx*8+7
    const int ty = t >> 4;        // row group: rows ty*4 .. ty*4+3
    const int row0 = blockIdx.x * 64;

    float acc[4][8];
#pragma unroll
    for (int i = 0; i < 4; ++i)
#pragma unroll
        for (int c = 0; c < 8; ++c) acc[i][c] = 0.f;

    for (int k0 = 0; k0 < INF; k0 += 32) {
        __syncthreads();
        // load h tile: thread t -> row t>>2, 8 consecutive k at (t&3)*8
        {
            const int r  = t >> 2;
            const int cb = (t & 3) * 8;
            const float* src = h + (size_t)(row0 + r) * INF + k0 + cb;
            float4 v0 = *reinterpret_cast<const float4*>(src);
            float4 v1 = *reinterpret_cast<const float4*>(src + 4);
            *reinterpret_cast<float4*>(&hs[r * APAD + cb])     = v0;
            *reinterpret_cast<float4*>(&hs[r * APAD + cb + 4]) = v1;
        }
        // load W tile: thread t -> k-row t>>3, 16 cols at (t&7)*16
        {
            const int kk = t >> 3;
            const int cb = (t & 7) * 16;
            const float* src = W + (size_t)(k0 + kk) * DF + cb;
#pragma unroll
            for (int k = 0; k < 4; ++k) {
                float4 v = *reinterpret_cast<const float4*>(src + k * 4);
                *reinterpret_cast<float4*>(&Ws[kk * DF + cb + k * 4]) = v;
            }
        }
        __syncthreads();
#pragma unroll
        for (int kk = 0; kk < 32; ++kk) {
            float av[4];
#pragma unroll
            for (int i = 0; i < 4; ++i) av[i] = hs[(ty * 4 + i) * APAD + kk];
            float4 b0 = *reinterpret_cast<const float4*>(&Ws[kk * DF + tx * 8]);
            float4 b1 = *reinterpret_cast<const float4*>(&Ws[kk * DF + tx * 8 + 4]);
#pragma unroll
            for (int i = 0; i < 4; ++i) {
                acc[i][0] = fmaf(av[i], b0.x, acc[i][0]);
                acc[i][1] = fmaf(av[i], b0.y, acc[i][1]);
                acc[i][2] = fmaf(av[i], b0.z, acc[i][2]);
                acc[i][3] = fmaf(av[i], b0.w, acc[i][3]);
                acc[i][4] = fmaf(av[i], b1.x, acc[i][4]);
                acc[i][5] = fmaf(av[i], b1.y, acc[i][5]);
                acc[i][6] = fmaf(av[i], b1.z, acc[i][6]);
                acc[i][7] = fmaf(av[i], b1.w, acc[i][7]);
            }
        }
    }
#pragma unroll
    for (int i = 0; i < 4; ++i) {
        float* dst = g_Wh + (size_t)(row0 + ty * 4 + i) * DF + tx * 8;
        float4 w0 = make_float4(acc[i][0], acc[i][1], acc[i][2], acc[i][3]);
        float4 w1 = make_float4(acc[i][4], acc[i][5], acc[i][6], acc[i][7]);
        *reinterpret_cast<float4*>(dst)     = w0;
        *reinterpret_cast<float4*>(dst + 4) = w1;
    }
}

// ===========================================================================
// Kernel B: per-node scalars. Wh1 = Wh . a[:128], Wh2 = Wh . a[128:],
// plus the 4 exp factors for the LeakyReLU-exp factorization.
// One warp per row.
// ===========================================================================
__global__ __launch_bounds__(256) void k_scalars(const float* __restrict__ a) {
    const int warp = (blockIdx.x * blockDim.x + threadIdx.x) >> 5;
    const int lane = threadIdx.x & 31;
    if (warp >= NROW) return;

    const float* whr = g_Wh + (size_t)warp * DF;
    float a1 = 0.f, a2 = 0.f;
#pragma unroll
    for (int q = 0; q < 4; ++q) {
        const int c = lane + q * 32;
        const float w = whr[c];
        a1 = fmaf(w, a[c],      a1);
        a2 = fmaf(w, a[DF + c], a2);
    }
#pragma unroll
    for (int off = 16; off > 0; off >>= 1) {
        a1 += __shfl_down_sync(0xffffffffu, a1, off);
        a2 += __shfl_down_sync(0xffffffffu, a2, off);
    }
    if (lane == 0) {
        g_Wh1[warp] = a1;
        g_Wh2[warp] = a2;
        g_E1 [warp] = expf(a1);
        g_E02[warp] = expf(0.2f * a1);
        g_F1 [warp] = expf(a2);
        g_F02[warp] = expf(0.2f * a2);
    }
}

// ===========================================================================
// Kernel C: fused masked-softmax attention + aggregation + ELU.
//   p(i,j) = adj ? ( t>0 ? E1[i]*F1[j] : E02[i]*F02[j] ) : 0,  t = Wh1[i]+Wh2[j]
//   out[i] = elu( (sum_j p * Wh[j]) / (sum_j p) )
// 384 CTAs x 32 rows, 128 threads, thread tile 4 rows x 8 cols, FFMA2 inner.
// ===========================================================================
__global__ __launch_bounds__(128) void k_gat(const int* __restrict__ adj,
                                             float* __restrict__ out) {
    __shared__ __align__(16) float sA[TJ * APAD];   // P tile   [jj][row], padded
    __shared__ __align__(16) float sB[TJ * DF];     // Wh tile  [jj][col]
    __shared__ float sSp[128];
    __shared__ float sS[RPC];

    const int t  = threadIdx.x;
    const int tx = t & 15;         // col group: cols tx*8 .. +7
    const int ty = t >> 4;         // row group: rows ty*4 .. +3
    const int row0 = blockIdx.x * RPC;

    // producer mapping: thread handles row pr, quarter pq (8 j's) of each tile
    const int pr = t >> 2;         // 0..31 local row
    const int pq = t & 3;          // j offsets pq*8 .. pq*8+7
    const float wh1r = g_Wh1[row0 + pr];
    const float e1r  = g_E1 [row0 + pr];
    const float e02r = g_E02[row0 + pr];
    const int* adjRow = adj + (size_t)(row0 + pr) * NROW;

    // B-stage mapping: thread stores Wh row bj, 4-float chunks at (t&3)*4 + k*16
    const int bj  = t >> 2;        // 0..31
    const int bc0 = (t & 3) * 4;

    ull acc[4][4];
#pragma unroll
    for (int i = 0; i < 4; ++i)
#pragma unroll
        for (int c = 0; c < 4; ++c) acc[i][c] = 0ull;
    float s_part = 0.f;

    int4   adjreg[2];
    float4 breg[8];

    // prologue prefetch: tile 0
    {
        adjreg[0] = *reinterpret_cast<const int4*>(adjRow + pq * 8);
        adjreg[1] = *reinterpret_cast<const int4*>(adjRow + pq * 8 + 4);
        const float* bsrc = g_Wh + (size_t)bj * DF + bc0;
#pragma unroll
        for (int k = 0; k < 8; ++k)
            breg[k] = *reinterpret_cast<const float4*>(bsrc + k * 16);
    }

    for (int tile = 0; tile < NT; ++tile) {
        const int j0 = tile * TJ;
        __syncthreads();   // previous tile's compute done -> SMEM reusable

        // ---- producer: compute P values for this tile from prefetched adj
#pragma unroll
        for (int k = 0; k < 2; ++k) {
            const int jj0 = pq * 8 + k * 4;
            const int4   av  = adjreg[k];
            const float4 w2  = *reinterpret_cast<const float4*>(g_Wh2 + j0 + jj0);
            const float4 f1  = *reinterpret_cast<const float4*>(g_F1  + j0 + jj0);
            const float4 f02 = *reinterpret_cast<const float4*>(g_F02 + j0 + jj0);

            float t0 = wh1r + w2.x, t1 = wh1r + w2.y, t2 = wh1r + w2.z, t3 = wh1r + w2.w;
            float p0 = (t0 > 0.f) ? e1r * f1.x : e02r * f02.x;
            float p1 = (t1 > 0.f) ? e1r * f1.y : e02r * f02.y;
            float p2 = (t2 > 0.f) ? e1r * f1.z : e02r * f02.z;
            float p3 = (t3 > 0.f) ? e1r * f1.w : e02r * f02.w;
            p0 = (av.x != 0) ? p0 : 0.f;
            p1 = (av.y != 0) ? p1 : 0.f;
            p2 = (av.z != 0) ? p2 : 0.f;
            p3 = (av.w != 0) ? p3 : 0.f;

            sA[(jj0 + 0) * APAD + pr] = p0;
            sA[(jj0 + 1) * APAD + pr] = p1;
            sA[(jj0 + 2) * APAD + pr] = p2;
            sA[(jj0 + 3) * APAD + pr] = p3;
            s_part += (p0 + p1) + (p2 + p3);
        }
        // ---- stage Wh tile from prefetched regs
#pragma unroll
        for (int k = 0; k < 8; ++k)
            *reinterpret_cast<float4*>(sB + bj * DF + bc0 + k * 16) = breg[k];

        // ---- prefetch next tile (overlaps with barrier + compute below)
        if (tile + 1 < NT) {
            const int j0n = j0 + TJ;
            adjreg[0] = *reinterpret_cast<const int4*>(adjRow + j0n + pq * 8);
            adjreg[1] = *reinterpret_cast<const int4*>(adjRow + j0n + pq * 8 + 4);
            const float* bsrc = g_Wh + (size_t)(j0n + bj) * DF + bc0;
#pragma unroll
            for (int k = 0; k < 8; ++k)
                breg[k] = *reinterpret_cast<const float4*>(bsrc + k * 16);
        }
        __syncthreads();   // sA / sB ready

        // ---- compute: rank-1 updates with packed f32x2 FMA
#pragma unroll 8
        for (int jj = 0; jj < TJ; ++jj) {
            const float4 pa = *reinterpret_cast<const float4*>(sA + jj * APAD + ty * 4);
            const ulonglong2 b01 = *reinterpret_cast<const ulonglong2*>(sB + jj * DF + tx * 8);
            const ulonglong2 b23 = *reinterpret_cast<const ulonglong2*>(sB + jj * DF + tx * 8 + 4);
            ull pd[4];
            pd[0] = pack2(pa.x); pd[1] = pack2(pa.y);
            pd[2] = pack2(pa.z); pd[3] = pack2(pa.w);
#pragma unroll
            for (int i = 0; i < 4; ++i) {
                fma2(acc[i][0], pd[i], b01.x);
                fma2(acc[i][1], pd[i], b01.y);
                fma2(acc[i][2], pd[i], b23.x);
                fma2(acc[i][3], pd[i], b23.y);
            }
        }
    }

    // ---- reduce row sums S (4 producer partials per row)
    sSp[t] = s_part;
    __syncthreads();
    if (t < RPC)
        sS[t] = (sSp[4 * t] + sSp[4 * t + 1]) + (sSp[4 * t + 2] + sSp[4 * t + 3]);
    __syncthreads();

    // ---- epilogue: normalize, ELU, store
#pragma unroll
    for (int i = 0; i < 4; ++i) {
        const int lr = ty * 4 + i;
        const float invS = 1.0f / sS[lr];
        float o[8];
#pragma unroll
        for (int c = 0; c < 4; ++c) {
            float2 v = unpack2(acc[i][c]);
            o[2 * c + 0] = v.x;
            o[2 * c + 1] = v.y;
        }
#pragma unroll
        for (int x = 0; x < 8; ++x) {
            float v = o[x] * invS;
            o[x] = (v > 0.f) ? v : expm1f(v);   // ELU (alpha = 1)
        }
        float* dst = out + (size_t)(row0 + lr) * DF + tx * 8;
        *reinterpret_cast<float4*>(dst)     = make_float4(o[0], o[1], o[2], o[3]);
        *reinterpret_cast<float4*>(dst + 4) = make_float4(o[4], o[5], o[6], o[7]);
    }
}

// ===========================================================================
extern "C" void kernel_launch(void* const* d_in, const int* in_sizes, int n_in,
                              void* d_out, int out_size) {
    const float* h   = (const float*)d_in[0];   // [12288, 256]
    const int*   adj = (const int*)  d_in[1];   // [12288, 12288]
    const float* W   = (const float*)d_in[2];   // [256, 128]
    const float* a   = (const float*)d_in[3];   // [256, 1]
    float* out = (float*)d_out;                 // [12288, 128]

    k_wh<<<NROW / 64, 256>>>(h, W);
    k_scalars<<<NROW / 8, 256>>>(a);            // 8 warps/block, 1 warp per row
    k_gat<<<NROW / RPC, 128>>>(adj, out);
}

// round 15
// speedup vs baseline: 1.7031x; 1.7031x over previous
#include <cuda_runtime.h>
#include <cuda_bf16.h>
#include <cstdint>
#include <cstddef>

// Problem constants
#define NROW 12288
#define INF  256
#define DF   128
#define KC   64                 // j-chunk (K of the big GEMM) per round
#define NCH  (NROW / KC)        // 192 chunks
#define MROW 128                // rows per CTA
#define APAD 36

// SMEM tile sizes (bytes)
#define ATILE 16384             // 128 rows x 128 B (64 bf16)
#define BTILE 16384             // 32 k-pair rows x 128 words
#define BUFB  (4 * 16384)       // Ahi, Alo, Bhi, Blo
#define SMEM_TILES (2 * BUFB)   // double buffered = 131072
#define SMEM_TOTAL (SMEM_TILES + 1024 + 512)

// ---------------- device scratch (static; no cudaMalloc) --------------------
__device__ __align__(16) float g_Wh [(size_t)NROW * DF];
__device__ __align__(16) float g_Wh1[NROW];
__device__ __align__(16) float g_Wh2[NROW];
__device__ __align__(16) float g_E1 [NROW];
__device__ __align__(16) float g_E02[NROW];
__device__ __align__(16) float g_F1 [NROW];
__device__ __align__(16) float g_F02[NROW];
// Wh in k-pair-packed bf16 hi/lo: word[(j/2)*128 + c] = {bf16 Wh[j][c], bf16 Wh[j+1][c]}
__device__ __align__(16) unsigned g_WhbP_hi[(size_t)(NROW / 2) * DF];
__device__ __align__(16) unsigned g_WhbP_lo[(size_t)(NROW / 2) * DF];

#define SW128(o) ((o) ^ (((o) >> 3) & 0x70))

// m16n8k16 row.col f32.bf16.bf16.f32 (HMMA — supported on plain compute_103)
__device__ __forceinline__ void mma16816(float* d, const unsigned* a,
                                         unsigned b0, unsigned b1) {
    asm volatile(
        "mma.sync.aligned.m16n8k16.row.col.f32.bf16.bf16.f32 "
        "{%0,%1,%2,%3}, {%4,%5,%6,%7}, {%8,%9}, {%0,%1,%2,%3};"
        : "+f"(d[0]), "+f"(d[1]), "+f"(d[2]), "+f"(d[3])
        : "r"(a[0]), "r"(a[1]), "r"(a[2]), "r"(a[3]), "r"(b0), "r"(b1));
}

// ===========================================================================
// Kernel A: Wh = h @ W.  32 rows x 128 cols per CTA, 256 threads, tile 2x8.
// Each thread owns a consecutive even/odd row pair -> emits k-pair-packed
// bf16 hi/lo words for the MMA B operand directly (coalesced stores).
// ===========================================================================
__global__ __launch_bounds__(256) void k_wh(const float* __restrict__ h,
                                            const float* __restrict__ W) {
    __shared__ __align__(16) float hs[32 * APAD];
    __shared__ __align__(16) float Ws[32 * DF];

    const int t  = threadIdx.x;
    const int tx = t & 15;       // cols tx*8 .. +7
    const int ty = t >> 4;       // rows ty*2 .. +1
    const int row0 = blockIdx.x * 32;

    float acc[2][8];
#pragma unroll
    for (int i = 0; i < 2; ++i)
#pragma unroll
        for (int c = 0; c < 8; ++c) acc[i][c] = 0.f;

    for (int k0 = 0; k0 < INF; k0 += 32) {
        __syncthreads();
        {   // h tile: 32 rows x 32 k
            const int r  = t >> 3;
            const int cb = (t & 7) * 4;
            float4 v = *reinterpret_cast<const float4*>(h + (size_t)(row0 + r) * INF + k0 + cb);
            *reinterpret_cast<float4*>(&hs[r * APAD + cb]) = v;
        }
        {   // W tile: 32 k x 128 cols
            const int kk = t >> 3;
            const int cb = (t & 7) * 16;
            const float* src = W + (size_t)(k0 + kk) * DF + cb;
#pragma unroll
            for (int k = 0; k < 4; ++k)
                *reinterpret_cast<float4*>(&Ws[kk * DF + cb + k * 4]) =
                    *reinterpret_cast<const float4*>(src + k * 4);
        }
        __syncthreads();
#pragma unroll
        for (int kk = 0; kk < 32; ++kk) {
            const float a0 = hs[(ty * 2 + 0) * APAD + kk];
            const float a1 = hs[(ty * 2 + 1) * APAD + kk];
            const float4 b0 = *reinterpret_cast<const float4*>(&Ws[kk * DF + tx * 8]);
            const float4 b1 = *reinterpret_cast<const float4*>(&Ws[kk * DF + tx * 8 + 4]);
            acc[0][0] = fmaf(a0, b0.x, acc[0][0]); acc[1][0] = fmaf(a1, b0.x, acc[1][0]);
            acc[0][1] = fmaf(a0, b0.y, acc[0][1]); acc[1][1] = fmaf(a1, b0.y, acc[1][1]);
            acc[0][2] = fmaf(a0, b0.z, acc[0][2]); acc[1][2] = fmaf(a1, b0.z, acc[1][2]);
            acc[0][3] = fmaf(a0, b0.w, acc[0][3]); acc[1][3] = fmaf(a1, b0.w, acc[1][3]);
            acc[0][4] = fmaf(a0, b1.x, acc[0][4]); acc[1][4] = fmaf(a1, b1.x, acc[1][4]);
            acc[0][5] = fmaf(a0, b1.y, acc[0][5]); acc[1][5] = fmaf(a1, b1.y, acc[1][5]);
            acc[0][6] = fmaf(a0, b1.z, acc[0][6]); acc[1][6] = fmaf(a1, b1.z, acc[1][6]);
            acc[0][7] = fmaf(a0, b1.w, acc[0][7]); acc[1][7] = fmaf(a1, b1.w, acc[1][7]);
        }
    }
    // fp32 Wh (used by k_scalars)
#pragma unroll
    for (int i = 0; i < 2; ++i) {
        float* dst = g_Wh + (size_t)(row0 + ty * 2 + i) * DF + tx * 8;
        *reinterpret_cast<float4*>(dst)     = make_float4(acc[i][0], acc[i][1], acc[i][2], acc[i][3]);
        *reinterpret_cast<float4*>(dst + 4) = make_float4(acc[i][4], acc[i][5], acc[i][6], acc[i][7]);
    }
    // k-pair-packed bf16 hi/lo words (B operand). Pair index = (row0+ty*2)/2.
    {
        const size_t jp = (size_t)(row0 + ty * 2) >> 1;
        unsigned hw[8], lw[8];
#pragma unroll
        for (int cc = 0; cc < 8; ++cc) {
            __nv_bfloat162 hi = __floats2bfloat162_rn(acc[0][cc], acc[1][cc]);
            const float q0 = __bfloat162float(hi.x);
            const float q1 = __bfloat162float(hi.y);
            __nv_bfloat162 lo = __floats2bfloat162_rn(acc[0][cc] - q0, acc[1][cc] - q1);
            hw[cc] = *reinterpret_cast<unsigned*>(&hi);
            lw[cc] = *reinterpret_cast<unsigned*>(&lo);
        }
        unsigned* dh = g_WhbP_hi + jp * DF + tx * 8;
        unsigned* dl = g_WhbP_lo + jp * DF + tx * 8;
        *reinterpret_cast<uint4*>(dh)     = make_uint4(hw[0], hw[1], hw[2], hw[3]);
        *reinterpret_cast<uint4*>(dh + 4) = make_uint4(hw[4], hw[5], hw[6], hw[7]);
        *reinterpret_cast<uint4*>(dl)     = make_uint4(lw[0], lw[1], lw[2], lw[3]);
        *reinterpret_cast<uint4*>(dl + 4) = make_uint4(lw[4], lw[5], lw[6], lw[7]);
    }
}

// ===========================================================================
// Kernel B: per-node scalars Wh1/Wh2 + exp factors. One warp per row.
// ===========================================================================
__global__ __launch_bounds__(256) void k_scalars(const float* __restrict__ a) {
    const int warp = (blockIdx.x * blockDim.x + threadIdx.x) >> 5;
    const int lane = threadIdx.x & 31;
    if (warp >= NROW) return;

    const float* whr = g_Wh + (size_t)warp * DF;
    float a1 = 0.f, a2 = 0.f;
#pragma unroll
    for (int q = 0; q < 4; ++q) {
        const int c = lane + q * 32;
        const float w = whr[c];
        a1 = fmaf(w, a[c],      a1);
        a2 = fmaf(w, a[DF + c], a2);
    }
#pragma unroll
    for (int off = 16; off > 0; off >>= 1) {
        a1 += __shfl_down_sync(0xffffffffu, a1, off);
        a2 += __shfl_down_sync(0xffffffffu, a2, off);
    }
    if (lane == 0) {
        g_Wh1[warp] = a1;
        g_Wh2[warp] = a2;
        g_E1 [warp] = expf(a1);
        g_E02[warp] = expf(0.2f * a1);
        g_F1 [warp] = expf(a2);
        g_F02[warp] = expf(0.2f * a2);
    }
}

// ===========================================================================
// Kernel C: fused GAT via warp-level bf16 HMMA (mma.sync m16n8k16), bf16x3
// split for ~fp32 accuracy. 96 CTAs x 128 rows, 256 threads = 8 warps (4Mx2N),
// warp tile 32 rows x 64 cols. Per 64-j chunk: produce P tile (hi/lo bf16,
// SW128), copy k-pair-packed B tile (hi/lo, XOR-swizzled), double-buffered;
// mma(c-1) overlaps produce(c). Epilogue: normalize by row sum, ELU, store.
// ===========================================================================
__global__ __launch_bounds__(256, 1) void k_gat_mma(const int* __restrict__ adj,
                                                    float* __restrict__ out) {
    extern __shared__ __align__(16) char smem[];
    float* sPart = reinterpret_cast<float*>(smem + SMEM_TILES);
    float* sRow  = reinterpret_cast<float*>(smem + SMEM_TILES + 1024);

    const int tid  = threadIdx.x;
    const int lane = tid & 31;
    const int wid  = tid >> 5;
    const int warp_m = wid >> 1;    // 0..3 -> rows warp_m*32
    const int warp_n = wid & 1;     // 0..1 -> cols warp_n*64
    const int row0 = blockIdx.x * MROW;

    // ---- producer mapping: thread -> local row r, k-half hh (32 j's)
    const int r  = tid >> 1;
    const int hh = tid & 1;
    const float wh1r = g_Wh1[row0 + r];
    const float e1r  = g_E1 [row0 + r];
    const float e02r = g_E02[row0 + r];
    const int* aptr = adj + (size_t)(row0 + r) * NROW + hh * 32;

    // ---- mma lane constants
    const int lq = lane >> 2;       // 0..7
    const int lr = lane & 3;        // 0..3

    float acc[2][8][4];             // [mtile][ntile][reg]
#pragma unroll
    for (int m = 0; m < 2; ++m)
#pragma unroll
        for (int n = 0; n < 8; ++n)
#pragma unroll
            for (int k = 0; k < 4; ++k) acc[m][n][k] = 0.f;
    float s = 0.f;

    int4 apf[8];
#pragma unroll
    for (int g = 0; g < 8; ++g)
        apf[g] = __ldcs(reinterpret_cast<const int4*>(aptr) + g);

#pragma unroll 1
    for (int c = 0; c <= NCH; ++c) {
        // ================= produce tile c into buffer c&1 ==================
        if (c < NCH) {
            const int j0 = c * KC;
            char* bufA_hi = smem + (size_t)(c & 1) * BUFB;
            char* bufA_lo = bufA_hi + ATILE;
#pragma unroll
            for (int g = 0; g < 8; ++g) {
                const int kk = hh * 32 + g * 4;    // local k 0..63
                const int gj = j0 + kk;
                const float4 w2  = *reinterpret_cast<const float4*>(g_Wh2 + gj);
                const float4 f1  = *reinterpret_cast<const float4*>(g_F1  + gj);
                const float4 f02 = *reinterpret_cast<const float4*>(g_F02 + gj);
                const int4 av = apf[g];
                float p0 = ((wh1r + w2.x) > 0.f) ? e1r * f1.x : e02r * f02.x;
                float p1 = ((wh1r + w2.y) > 0.f) ? e1r * f1.y : e02r * f02.y;
                float p2 = ((wh1r + w2.z) > 0.f) ? e1r * f1.z : e02r * f02.z;
                float p3 = ((wh1r + w2.w) > 0.f) ? e1r * f1.w : e02r * f02.w;
                p0 = av.x ? p0 : 0.f;
                p1 = av.y ? p1 : 0.f;
                p2 = av.z ? p2 : 0.f;
                p3 = av.w ? p3 : 0.f;
                s += (p0 + p1) + (p2 + p3);

                __nv_bfloat162 h01 = __floats2bfloat162_rn(p0, p1);
                __nv_bfloat162 h23 = __floats2bfloat162_rn(p2, p3);
                const float q0 = __bfloat162float(h01.x), q1 = __bfloat162float(h01.y);
                const float q2 = __bfloat162float(h23.x), q3 = __bfloat162float(h23.y);
                __nv_bfloat162 l01 = __floats2bfloat162_rn(p0 - q0, p1 - q1);
                __nv_bfloat162 l23 = __floats2bfloat162_rn(p2 - q2, p3 - q3);

                const unsigned off = SW128((unsigned)(r * 128 + kk * 2));
                uint2 sh, sl;
                sh.x = *reinterpret_cast<unsigned*>(&h01);
                sh.y = *reinterpret_cast<unsigned*>(&h23);
                sl.x = *reinterpret_cast<unsigned*>(&l01);
                sl.y = *reinterpret_cast<unsigned*>(&l23);
                *reinterpret_cast<uint2*>(bufA_hi + off) = sh;
                *reinterpret_cast<uint2*>(bufA_lo + off) = sl;
            }
            // ---- B tile copy: k-pair-packed words, XOR swizzle (n ^ (k2&3)*8)
            {
                char* bufB_hi = bufA_hi + 2 * ATILE;
                char* bufB_lo = bufB_hi + BTILE;
                const size_t gb = (size_t)(j0 >> 1) * DF;
#pragma unroll
                for (int q = 0; q < 4; ++q) {
                    const int idx = tid + q * 256;          // 0..1023 int4 slots
                    const int k2  = idx >> 5;               // 0..31
                    const int n0  = (idx & 31) * 4;         // 0..124
                    const int nsw = n0 ^ ((k2 & 3) << 3);
                    const uint4 vh = *reinterpret_cast<const uint4*>(g_WhbP_hi + gb + k2 * DF + n0);
                    const uint4 vl = *reinterpret_cast<const uint4*>(g_WhbP_lo + gb + k2 * DF + n0);
                    *reinterpret_cast<uint4*>(bufB_hi + k2 * 512 + nsw * 4) = vh;
                    *reinterpret_cast<uint4*>(bufB_lo + k2 * 512 + nsw * 4) = vl;
                }
            }
            // ---- prefetch next chunk's adj (covered by mma below)
            if (c + 1 < NCH) {
#pragma unroll
                for (int g = 0; g < 8; ++g)
                    apf[g] = __ldcs(reinterpret_cast<const int4*>(aptr + (c + 1) * KC) + g);
            }
        }

        // ================= mma on tile c-1 (buffer (c-1)&1) ================
        if (c > 0) {
            char* bufA_hi = smem + (size_t)((c - 1) & 1) * BUFB;
            char* bufA_lo = bufA_hi + ATILE;
            char* bufB_hi = bufA_hi + 2 * ATILE;
            char* bufB_lo = bufB_hi + BTILE;
#pragma unroll
            for (int ks = 0; ks < 4; ++ks) {
                unsigned ah[2][4], al[2][4];
#pragma unroll
                for (int m = 0; m < 2; ++m) {
                    const int ra = warp_m * 32 + m * 16 + lq;
                    const unsigned o0 = SW128((unsigned)(ra * 128 + (ks * 8 + lr) * 4));
                    const unsigned o1 = SW128((unsigned)((ra + 8) * 128 + (ks * 8 + lr) * 4));
                    const unsigned o2 = SW128((unsigned)(ra * 128 + (ks * 8 + 4 + lr) * 4));
                    const unsigned o3 = SW128((unsigned)((ra + 8) * 128 + (ks * 8 + 4 + lr) * 4));
                    ah[m][0] = *reinterpret_cast<const unsigned*>(bufA_hi + o0);
                    ah[m][1] = *reinterpret_cast<const unsigned*>(bufA_hi + o1);
                    ah[m][2] = *reinterpret_cast<const unsigned*>(bufA_hi + o2);
                    ah[m][3] = *reinterpret_cast<const unsigned*>(bufA_hi + o3);
                    al[m][0] = *reinterpret_cast<const unsigned*>(bufA_lo + o0);
                    al[m][1] = *reinterpret_cast<const unsigned*>(bufA_lo + o1);
                    al[m][2] = *reinterpret_cast<const unsigned*>(bufA_lo + o2);
                    al[m][3] = *reinterpret_cast<const unsigned*>(bufA_lo + o3);
                }
#pragma unroll
                for (int nt = 0; nt < 8; ++nt) {
                    const int n  = warp_n * 64 + nt * 8 + lq;
                    const int k2a = ks * 8 + lr;
                    const int k2b = k2a + 4;
                    const unsigned oba = (unsigned)(k2a * 512 + (n ^ ((k2a & 3) << 3)) * 4);
                    const unsigned obb = (unsigned)(k2b * 512 + (n ^ ((k2b & 3) << 3)) * 4);
                    const unsigned bh0 = *reinterpret_cast<const unsigned*>(bufB_hi + oba);
                    const unsigned bh1 = *reinterpret_cast<const unsigned*>(bufB_hi + obb);
                    const unsigned bl0 = *reinterpret_cast<const unsigned*>(bufB_lo + oba);
                    const unsigned bl1 = *reinterpret_cast<const unsigned*>(bufB_lo + obb);
#pragma unroll
                    for (int m = 0; m < 2; ++m) {
                        mma16816(acc[m][nt], ah[m], bh0, bh1);
                        mma16816(acc[m][nt], ah[m], bl0, bl1);
                        mma16816(acc[m][nt], al[m], bh0, bh1);
                    }
                }
            }
        }
        __syncthreads();
    }

    // ---- row sums (2 producer partials per row)
    sPart[tid] = s;
    __syncthreads();
    if (tid < MROW) sRow[tid] = sPart[2 * tid] + sPart[2 * tid + 1];
    __syncthreads();

    // ---- epilogue: normalize, ELU, store (d-frag layout)
#pragma unroll
    for (int m = 0; m < 2; ++m) {
        const int rl0 = warp_m * 32 + m * 16 + lq;       // rows rl0, rl0+8
        const float is0 = 1.0f / sRow[rl0];
        const float is1 = 1.0f / sRow[rl0 + 8];
#pragma unroll
        for (int nt = 0; nt < 8; ++nt) {
            const int col = warp_n * 64 + nt * 8 + lr * 2;
            float v0 = acc[m][nt][0] * is0;
            float v1 = acc[m][nt][1] * is0;
            float v2 = acc[m][nt][2] * is1;
            float v3 = acc[m][nt][3] * is1;
            v0 = (v0 > 0.f) ? v0 : expm1f(v0);
            v1 = (v1 > 0.f) ? v1 : expm1f(v1);
            v2 = (v2 > 0.f) ? v2 : expm1f(v2);
            v3 = (v3 > 0.f) ? v3 : expm1f(v3);
            *reinterpret_cast<float2*>(out + (size_t)(row0 + rl0) * DF + col)     = make_float2(v0, v1);
            *reinterpret_cast<float2*>(out + (size_t)(row0 + rl0 + 8) * DF + col) = make_float2(v2, v3);
        }
    }
}

// ===========================================================================
extern "C" void kernel_launch(void* const* d_in, const int* in_sizes, int n_in,
                              void* d_out, int out_size) {
    const float* h   = (const float*)d_in[0];   // [12288, 256]
    const int*   adj = (const int*)  d_in[1];   // [12288, 12288]
    const float* W   = (const float*)d_in[2];   // [256, 128]
    const float* a   = (const float*)d_in[3];   // [256, 1]
    float* out = (float*)d_out;                 // [12288, 128]

    cudaFuncSetAttribute(k_gat_mma, cudaFuncAttributeMaxDynamicSharedMemorySize, SMEM_TOTAL);

    k_wh<<<NROW / 32, 256>>>(h, W);
    k_scalars<<<NROW / 8, 256>>>(a);
    k_gat_mma<<<NROW / MROW, 256, SMEM_TOTAL>>>(adj, out);
}